// round 7
// baseline (speedup 1.0000x reference)
#include <cuda_runtime.h>
#include <cstdint>

#define SEQ 2048
#define HD 64
#define NBH 32
#define TOPK 32
#define QR 16           // q-rows per CTA
#define THREADS 256
#define JC 1024         // j-chunk
#define DC 16           // d-chunk
#define LCAP 128
#define CCAP 256

typedef unsigned long long u64;

// Dynamic smem layout (bytes)
#define OFF_SROW  0         // uint [QR][SEQ]       131072
#define OFF_KST   131072    // float[DC][JC]         65536
#define OFF_QD    196608    // u64  [HD][QR]          8192
#define OFF_HIST  204800    // uint [8][256]          8192
#define OFF_CAND  212992    // u16  [8][CCAP]         4096
#define OFF_LIST  217088    // int  [8][LCAP]         4096
#define OFF_PLIST 221184    // float[8][LCAP]         4096
#define SMEM_TOTAL 225280

__device__ __forceinline__ u64 dup2(float x) {
    u64 r; asm("mov.b64 %0, {%1, %1};" : "=l"(r) : "f"(x)); return r;
}
__device__ __forceinline__ void fma2(u64& c, u64 a, u64 b) {
    asm("fma.rn.f32x2 %0, %1, %2, %0;" : "+l"(c) : "l"(a), "l"(b));
}
__device__ __forceinline__ unsigned fkey(float f) {
    unsigned u = __float_as_uint(f);
    return (u & 0x80000000u) ? ~u : (u | 0x80000000u);
}
__device__ __forceinline__ float unfkey(unsigned k) {
    return (k & 0x80000000u) ? __uint_as_float(k & 0x7FFFFFFFu) : __uint_as_float(~k);
}

__global__ __launch_bounds__(THREADS) void fused_attn_kernel(
    const float* __restrict__ q, const float* __restrict__ k,
    const float* __restrict__ v,
    float* __restrict__ ctx, float* __restrict__ attn, float* __restrict__ maskp)
{
    extern __shared__ char smem[];
    unsigned* Srow = (unsigned*)(smem + OFF_SROW);
    float*    KsT  = (float*)(smem + OFF_KST);
    u64*      Qd   = (u64*)(smem + OFF_QD);
    unsigned* hist = (unsigned*)(smem + OFF_HIST);
    unsigned short* cand = (unsigned short*)(smem + OFF_CAND);
    int*      list = (int*)(smem + OFF_LIST);
    float*    plist= (float*)(smem + OFF_PLIST);

    const int t = threadIdx.x;
    const int qt = blockIdx.x;       // 0..127
    const int bh = blockIdx.y;       // 0..31
    const float* qb = q + ((size_t)bh * SEQ + qt * QR) * HD;
    const float* kb = k + (size_t)bh * SEQ * HD;

    // ---- Stage Q (16 x 64), scaled by 1/8, duplicated pairs for f32x2 ----
    {
        int row = t >> 4, d4 = t & 15;
        float4 val = ((const float4*)(qb + row * HD))[d4];
        Qd[(d4 * 4 + 0) * QR + row] = dup2(val.x * 0.125f);
        Qd[(d4 * 4 + 1) * QR + row] = dup2(val.y * 0.125f);
        Qd[(d4 * 4 + 2) * QR + row] = dup2(val.z * 0.125f);
        Qd[(d4 * 4 + 3) * QR + row] = dup2(val.w * 0.125f);
    }

    // ---- GEMM: 16 x 2048 scores, 8x8 microtile per thread ----
    const int ti = t >> 7;           // 0..1  -> i0 = ti*8
    const int tj = t & 127;          // 0..127 -> j0 = tj*8
    const int i0 = ti * 8;

    for (int jc = 0; jc < SEQ / JC; jc++) {
        u64 acc[8][4];
#pragma unroll
        for (int i = 0; i < 8; i++)
#pragma unroll
            for (int p = 0; p < 4; p++) acc[i][p] = 0ull;

        for (int dcb = 0; dcb < HD / DC; dcb++) {
            __syncthreads();   // protect KsT (and Qd on first pass)
            // Stage K chunk: rows jc*JC..+1023, d = dcb*DC..+15, swizzled transpose
#pragma unroll
            for (int it = 0; it < 16; it++) {
                int idx = t + THREADS * it;         // 0..4095
                int row = idx >> 2, d4 = idx & 3;
                float4 val = ((const float4*)(kb + (size_t)(jc * JC + row) * HD))[dcb * 4 + d4];
                int jb = row >> 2, jr = row & 3;
#pragma unroll
                for (int cc = 0; cc < 4; cc++) {
                    float fv = (cc == 0) ? val.x : (cc == 1) ? val.y : (cc == 2) ? val.z : val.w;
                    int dl = d4 * 4 + cc;
                    KsT[dl * JC + ((jb ^ (dl & 7)) << 2) + jr] = fv;
                }
            }
            __syncthreads();
            // Compute 16 d-steps
#pragma unroll
            for (int dl = 0; dl < DC; dl++) {
                int d = dcb * DC + dl;
                const ulonglong2* qa = (const ulonglong2*)(Qd + d * QR + i0);
                ulonglong2 a01 = qa[0], a23 = qa[1], a45 = qa[2], a67 = qa[3];
                const int s = dl & 7;
                const ulonglong2* kr = (const ulonglong2*)(KsT + dl * JC);
                ulonglong2 bA = kr[(tj * 2) ^ s];
                ulonglong2 bB = kr[(tj * 2 + 1) ^ s];
                fma2(acc[0][0], a01.x, bA.x); fma2(acc[0][1], a01.x, bA.y);
                fma2(acc[0][2], a01.x, bB.x); fma2(acc[0][3], a01.x, bB.y);
                fma2(acc[1][0], a01.y, bA.x); fma2(acc[1][1], a01.y, bA.y);
                fma2(acc[1][2], a01.y, bB.x); fma2(acc[1][3], a01.y, bB.y);
                fma2(acc[2][0], a23.x, bA.x); fma2(acc[2][1], a23.x, bA.y);
                fma2(acc[2][2], a23.x, bB.x); fma2(acc[2][3], a23.x, bB.y);
                fma2(acc[3][0], a23.y, bA.x); fma2(acc[3][1], a23.y, bA.y);
                fma2(acc[3][2], a23.y, bB.x); fma2(acc[3][3], a23.y, bB.y);
                fma2(acc[4][0], a45.x, bA.x); fma2(acc[4][1], a45.x, bA.y);
                fma2(acc[4][2], a45.x, bB.x); fma2(acc[4][3], a45.x, bB.y);
                fma2(acc[5][0], a45.y, bA.x); fma2(acc[5][1], a45.y, bA.y);
                fma2(acc[5][2], a45.y, bB.x); fma2(acc[5][3], a45.y, bB.y);
                fma2(acc[6][0], a67.x, bA.x); fma2(acc[6][1], a67.x, bA.y);
                fma2(acc[6][2], a67.x, bB.x); fma2(acc[6][3], a67.x, bB.y);
                fma2(acc[7][0], a67.y, bA.x); fma2(acc[7][1], a67.y, bA.y);
                fma2(acc[7][2], a67.y, bB.x); fma2(acc[7][3], a67.y, bB.y);
            }
        }
        // Store scores for this j-chunk as order-preserving keys
#pragma unroll
        for (int i = 0; i < 8; i++) {
            float2 f0 = *(float2*)&acc[i][0];
            float2 f1 = *(float2*)&acc[i][1];
            float2 f2 = *(float2*)&acc[i][2];
            float2 f3 = *(float2*)&acc[i][3];
            uint4 lo = make_uint4(fkey(f0.x), fkey(f0.y), fkey(f1.x), fkey(f1.y));
            uint4 hi = make_uint4(fkey(f2.x), fkey(f2.y), fkey(f3.x), fkey(f3.y));
            uint4* dst = (uint4*)(Srow + (size_t)(i0 + i) * SEQ) + jc * (JC / 4) + tj * 2;
            dst[0] = lo; dst[1] = hi;
        }
    }
    __syncthreads();   // all score rows complete

    // ---- Select / softmax / output phase: warp w handles rows 2w, 2w+1 ----
    const int w = t >> 5;
    const int lane = t & 31;
    unsigned* H = hist + w * 256;
    unsigned short* C = cand + w * CCAP;
    int* L = list + w * LCAP;
    float* P = plist + w * LCAP;
    const float* vb = v + (size_t)bh * SEQ * HD;

    for (int rr = 0; rr < 2; rr++) {
        const int r = 2 * w + rr;
        unsigned* key = Srow + (size_t)r * SEQ;
        const size_t R = (size_t)bh * SEQ + qt * QR + r;

        // Pass 1: max key + top-byte histogram
#pragma unroll
        for (int e = 0; e < 8; e++) H[lane + 32 * e] = 0;
        __syncwarp();
        unsigned mk = 0;
        for (int it = 0; it < 64; it++) {
            unsigned u = key[lane + 32 * it];
            mk = umax(mk, u);
            atomicAdd(&H[u >> 24], 1u);
        }
#pragma unroll
        for (int off = 16; off >= 1; off >>= 1)
            mk = umax(mk, __shfl_xor_sync(0xffffffffu, mk, off));
        const float m = unfkey(mk);
        __syncwarp();

        // Round 1: pick top byte containing the 32nd-largest
        unsigned prefix, prefmask, kk = TOPK, b1;
        {
            unsigned p = 0;
#pragma unroll
            for (int b = 0; b < 8; b++) p += H[lane * 8 + b];
            unsigned S = p;
#pragma unroll
            for (int off = 1; off < 32; off <<= 1) {
                unsigned tv = __shfl_down_sync(0xffffffffu, S, off);
                if (lane + off < 32) S += tv;
            }
            unsigned sufExcl = S - p;
            bool mine = (S >= kk) && (sufExcl < kk);
            unsigned bal = __ballot_sync(0xffffffffu, mine);
            int src = __ffs(bal) - 1;
            unsigned chosen = 0, newk = 0;
            if (mine) {
                unsigned cum = sufExcl;
#pragma unroll
                for (int b = 7; b >= 0; b--) {
                    unsigned h = H[lane * 8 + b];
                    if (cum + h >= kk) { chosen = lane * 8 + b; newk = kk - cum; break; }
                    cum += h;
                }
            }
            b1 = __shfl_sync(0xffffffffu, chosen, src);
            kk = __shfl_sync(0xffffffffu, newk, src);
            prefix = b1 << 24;
            prefmask = 0xFF000000u;
        }
        __syncwarp();

        // Compact candidates (top byte == b1), deterministic order
        int cbase = 0;
        for (int it = 0; it < 64; it++) {
            int j = lane + 32 * it;
            bool isc = (key[j] >> 24) == b1;
            unsigned bal = __ballot_sync(0xffffffffu, isc);
            if (isc) {
                int pos = cbase + __popc(bal & ((1u << lane) - 1u));
                if (pos < CCAP) C[pos] = (unsigned short)j;
            }
            cbase += __popc(bal);
        }
        __syncwarp();
        const bool useCand = (cbase <= CCAP);
        const int c = cbase < CCAP ? cbase : CCAP;

        // Rounds 2-4
#pragma unroll
        for (int shift = 16; shift >= 0; shift -= 8) {
#pragma unroll
            for (int e = 0; e < 8; e++) H[lane + 32 * e] = 0;
            __syncwarp();
            if (useCand) {
                for (int e = lane; e < c; e += 32) {
                    unsigned u = key[C[e]];
                    if ((u & prefmask) == prefix)
                        atomicAdd(&H[(u >> shift) & 255u], 1u);
                }
            } else {
                for (int it = 0; it < 64; it++) {
                    unsigned u = key[lane + 32 * it];
                    if ((u & prefmask) == prefix)
                        atomicAdd(&H[(u >> shift) & 255u], 1u);
                }
            }
            __syncwarp();
            unsigned p = 0;
#pragma unroll
            for (int b = 0; b < 8; b++) p += H[lane * 8 + b];
            unsigned S = p;
#pragma unroll
            for (int off = 1; off < 32; off <<= 1) {
                unsigned tv = __shfl_down_sync(0xffffffffu, S, off);
                if (lane + off < 32) S += tv;
            }
            unsigned sufExcl = S - p;
            bool mine = (S >= kk) && (sufExcl < kk);
            unsigned bal = __ballot_sync(0xffffffffu, mine);
            int src = __ffs(bal) - 1;
            unsigned chosen = 0, newk = 0;
            if (mine) {
                unsigned cum = sufExcl;
#pragma unroll
                for (int b = 7; b >= 0; b--) {
                    unsigned h = H[lane * 8 + b];
                    if (cum + h >= kk) { chosen = lane * 8 + b; newk = kk - cum; break; }
                    cum += h;
                }
            }
            chosen = __shfl_sync(0xffffffffu, chosen, src);
            kk = __shfl_sync(0xffffffffu, newk, src);
            prefix |= chosen << shift;
            prefmask |= 0xFFu << shift;
            __syncwarp();
        }
        const unsigned tkey = prefix;   // exact key of the 32nd-largest

        // Streaming fills: attn = 0, mask = 1
        if (attn) {
            float4* a4 = (float4*)(attn + R * SEQ);
            const float4 z4 = make_float4(0.f, 0.f, 0.f, 0.f);
#pragma unroll
            for (int it = 0; it < 16; it++) a4[lane + 32 * it] = z4;
        }
        if (maskp) {
            float4* m4 = (float4*)(maskp + R * SEQ);
            const float4 o4 = make_float4(1.f, 1.f, 1.f, 1.f);
#pragma unroll
            for (int it = 0; it < 16; it++) m4[lane + 32 * it] = o4;
        }

        // Deterministic compaction of kept (key >= tkey)
        int base = 0;
        for (int it = 0; it < 64; it++) {
            int j = lane + 32 * it;
            bool keep = key[j] >= tkey;
            unsigned bal = __ballot_sync(0xffffffffu, keep);
            if (keep) {
                int pos = base + __popc(bal & ((1u << lane) - 1u));
                if (pos < LCAP) L[pos] = j;
            }
            base += __popc(bal);
        }
        __syncwarp();
        const int n = base < LCAP ? base : LCAP;

        // exp on kept entries; deterministic partition sum
        float lsum = 0.f;
        for (int e = lane; e < n; e += 32) {
            float s = unfkey(key[L[e]]);
            float p = __expf(s - m);
            P[e] = p;
            lsum += p;
        }
#pragma unroll
        for (int off = 16; off >= 1; off >>= 1)
            lsum += __shfl_xor_sync(0xffffffffu, lsum, off);
        const float inv = 1.0f / lsum;
        __syncwarp();

        // Scatter kept attn / mask=0; gather-accumulate context
        float acc0 = 0.f, acc1 = 0.f;
        float* arow = attn ? attn + R * SEQ : (float*)0;
        float* mrow = maskp ? maskp + R * SEQ : (float*)0;
        for (int e = 0; e < n; e++) {
            int j = L[e];
            float wgt = P[e] * inv;
            if (lane == 0) {
                if (arow) arow[j] = wgt;
                if (mrow) mrow[j] = 0.f;
            }
            acc0 += wgt * vb[j * HD + lane];
            acc1 += wgt * vb[j * HD + lane + 32];
        }
        if (ctx) {
            ctx[R * HD + lane] = acc0;
            ctx[R * HD + lane + 32] = acc1;
        }
        __syncwarp();
    }
}

// ---------------------------------------------------------------------------
extern "C" void kernel_launch(void* const* d_in, const int* in_sizes, int n_in,
                              void* d_out, int out_size)
{
    if (n_in < 3 || !d_out) return;
    const float* q = (const float*)d_in[0];
    const float* k = (const float*)d_in[1];
    const float* v = (const float*)d_in[2];
    float* out = (float*)d_out;

    const size_t nctx = (size_t)NBH * SEQ * HD;        //   4,194,304
    const size_t nattn = (size_t)NBH * SEQ * SEQ;      // 134,217,728
    float* ctx = 0; float* attn = 0; float* maskp = 0;
    const size_t osz = (size_t)out_size;
    if (osz >= nctx + 2 * nattn) {            // (context, attn, mask) fp32
        ctx = out; attn = out + nctx; maskp = out + nctx + nattn;
    } else if (osz >= nctx + nattn) {
        ctx = out; attn = out + nctx;
    } else {
        attn = out;
    }

    static bool attr_done = false;
    if (!attr_done) {
        cudaFuncSetAttribute(fused_attn_kernel,
                             cudaFuncAttributeMaxDynamicSharedMemorySize, SMEM_TOTAL);
        attr_done = true;
    }
    fused_attn_kernel<<<dim3(SEQ / QR, NBH), THREADS, SMEM_TOTAL>>>(
        q, k, v, ctx, attn, maskp);
}

// round 8
// speedup vs baseline: 1.5353x; 1.5353x over previous
#include <cuda_runtime.h>
#include <mma.h>
#include <cstdint>

using namespace nvcuda;

#define SEQ 2048
#define HD 64
#define NBH 32
#define TOPK 32
#define WPB 4
#define LCAP 128
#define CAND_CAP 512

#define TLD 72                 // smem leading dim for 64-wide tiles (+8 pad)
#define SCORE_SMEM (4 * 128 * TLD * 4)   // Ah, Al, Bh, Bl = 147456 B

__device__ __forceinline__ float tf32r(float x) {
    unsigned u;
    asm("cvt.rna.tf32.f32 %0, %1;" : "=r"(u) : "f"(x));
    return __uint_as_float(u);
}
__device__ __forceinline__ unsigned fkey(float f) {
    unsigned u = __float_as_uint(f);
    return (u & 0x80000000u) ? ~u : (u | 0x80000000u);
}
__device__ __forceinline__ float unfkey(unsigned k) {
    return (k & 0x80000000u) ? __uint_as_float(k & 0x7FFFFFFFu) : __uint_as_float(~k);
}

// ---------------------------------------------------------------------------
// Kernel 1: scores[bh,i,j] = (q/8) . k  via tf32 split-precision tensor cores.
// 128(i) x 128(j) tile per CTA, 256 threads = 8 warps (2 x 4), warp tile 64x32.
// S = Ah*Bh + Ah*Bl + Al*Bh  (lo*lo dropped, ~2^-22 relative).
// Also prefills mask = 1.0f over its tile.
// ---------------------------------------------------------------------------
__global__ __launch_bounds__(256) void score_kernel(
    const float* __restrict__ q, const float* __restrict__ k,
    float* __restrict__ scores, float* __restrict__ maskp)
{
    extern __shared__ float sm[];
    float* Ah = sm;                      // [128][TLD]
    float* Al = Ah + 128 * TLD;
    float* Bh = Al + 128 * TLD;
    float* Bl = Bh + 128 * TLD;

    const int t = threadIdx.x;
    const int bh = blockIdx.z;
    const int iBase = blockIdx.y * 128;
    const int jBase = blockIdx.x * 128;
    const float* qb = q + ((size_t)bh * SEQ + iBase) * HD;
    const float* kb = k + ((size_t)bh * SEQ + jBase) * HD;

    // Stage tiles: 128 rows x 16 float4 = 2048 float4 each; 8 per thread.
#pragma unroll
    for (int it = 0; it < 8; it++) {
        int idx = t + 256 * it;
        int row = idx >> 4, c4 = idx & 15;
        float4 qa = ((const float4*)(qb + row * HD))[c4];
        qa.x *= 0.125f; qa.y *= 0.125f; qa.z *= 0.125f; qa.w *= 0.125f;
        float h0 = tf32r(qa.x), h1 = tf32r(qa.y), h2 = tf32r(qa.z), h3 = tf32r(qa.w);
        int o = row * TLD + c4 * 4;
        Ah[o + 0] = h0; Ah[o + 1] = h1; Ah[o + 2] = h2; Ah[o + 3] = h3;
        Al[o + 0] = tf32r(qa.x - h0); Al[o + 1] = tf32r(qa.y - h1);
        Al[o + 2] = tf32r(qa.z - h2); Al[o + 3] = tf32r(qa.w - h3);

        float4 ka = ((const float4*)(kb + row * HD))[c4];
        float g0 = tf32r(ka.x), g1 = tf32r(ka.y), g2 = tf32r(ka.z), g3 = tf32r(ka.w);
        Bh[o + 0] = g0; Bh[o + 1] = g1; Bh[o + 2] = g2; Bh[o + 3] = g3;
        Bl[o + 0] = tf32r(ka.x - g0); Bl[o + 1] = tf32r(ka.y - g1);
        Bl[o + 2] = tf32r(ka.z - g2); Bl[o + 3] = tf32r(ka.w - g3);
    }
    __syncthreads();

    const int w = t >> 5;
    const int wi = w >> 2;        // 0..1 -> i offset wi*64
    const int wj = w & 3;         // 0..3 -> j offset wj*32

    wmma::fragment<wmma::accumulator, 16, 16, 8, float> c[4][2];
#pragma unroll
    for (int ma = 0; ma < 4; ma++)
#pragma unroll
        for (int nb = 0; nb < 2; nb++) wmma::fill_fragment(c[ma][nb], 0.0f);

#pragma unroll
    for (int ks = 0; ks < 8; ks++) {
        const int k0 = ks * 8;
        wmma::fragment<wmma::matrix_a, 16, 16, 8, wmma::precision::tf32, wmma::row_major> ah[4], al[4];
        wmma::fragment<wmma::matrix_b, 16, 16, 8, wmma::precision::tf32, wmma::col_major> bhf[2], blf[2];
#pragma unroll
        for (int ma = 0; ma < 4; ma++) {
            const float* base = Ah + (wi * 64 + ma * 16) * TLD + k0;
            wmma::load_matrix_sync(ah[ma], base, TLD);
            wmma::load_matrix_sync(al[ma], base + 128 * TLD, TLD);  // Al
        }
#pragma unroll
        for (int nb = 0; nb < 2; nb++) {
            const float* base = Bh + (wj * 32 + nb * 16) * TLD + k0;
            wmma::load_matrix_sync(bhf[nb], base, TLD);
            wmma::load_matrix_sync(blf[nb], base + 128 * TLD, TLD); // Bl
        }
#pragma unroll
        for (int ma = 0; ma < 4; ma++)
#pragma unroll
            for (int nb = 0; nb < 2; nb++) {
                wmma::mma_sync(c[ma][nb], ah[ma], bhf[nb], c[ma][nb]);
                wmma::mma_sync(c[ma][nb], ah[ma], blf[nb], c[ma][nb]);
                wmma::mma_sync(c[ma][nb], al[ma], bhf[nb], c[ma][nb]);
            }
    }

    // Store 64x32 warp tile
#pragma unroll
    for (int ma = 0; ma < 4; ma++)
#pragma unroll
        for (int nb = 0; nb < 2; nb++) {
            float* dst = scores + ((size_t)bh * SEQ + iBase + wi * 64 + ma * 16) * SEQ
                       + jBase + wj * 32 + nb * 16;
            wmma::store_matrix_sync(dst, c[ma][nb], SEQ, wmma::mem_row_major);
        }

    // Prefill mask = 1 over this 128x128 tile
    if (maskp) {
        const float4 one4 = make_float4(1.f, 1.f, 1.f, 1.f);
#pragma unroll
        for (int it = 0; it < 16; it++) {
            int idx = t + 256 * it;            // 0..4095 -> 128 rows x 32 float4
            int row = idx >> 5, c4 = idx & 31;
            float4* mo = (float4*)(maskp + ((size_t)bh * SEQ + iBase + row) * SEQ + jBase) + c4;
            *mo = one4;
        }
    }
}

// ---------------------------------------------------------------------------
// Kernel 2 (verbatim from R5, measured 549 us): warp-per-row exact radix
// select of the 32nd-largest, masked softmax, sparse context, mask scatter.
// ---------------------------------------------------------------------------
__global__ __launch_bounds__(WPB * 32) void finalize_kernel(
    const float* __restrict__ v, const float* __restrict__ scores,
    float* __restrict__ ctx, float* __restrict__ attn, float* __restrict__ maskp)
{
    __shared__ unsigned srow[WPB][SEQ];
    __shared__ unsigned hist[WPB][256];
    __shared__ unsigned short cand[WPB][CAND_CAP];
    __shared__ int list[WPB][LCAP];
    __shared__ float plist[WPB][LCAP];

    const int w = threadIdx.x >> 5;
    const int lane = threadIdx.x & 31;
    const size_t R = (size_t)blockIdx.x * WPB + w;
    const int bh = (int)(R >> 11);

    const float4* g4 = (const float4*)(scores + R * SEQ);
    uint4* s4 = (uint4*)srow[w];
    float m = __int_as_float(0xff800000);
#pragma unroll
    for (int it = 0; it < 16; it++) {
        float4 val = g4[lane + 32 * it];
        s4[lane + 32 * it] = make_uint4(fkey(val.x), fkey(val.y), fkey(val.z), fkey(val.w));
        m = fmaxf(m, fmaxf(fmaxf(val.x, val.y), fmaxf(val.z, val.w)));
    }
#pragma unroll
    for (int off = 16; off >= 1; off >>= 1)
        m = fmaxf(m, __shfl_xor_sync(0xffffffffu, m, off));
    __syncwarp();

#pragma unroll
    for (int e = 0; e < 8; e++) hist[w][lane + 32 * e] = 0;
    __syncwarp();
    for (int it = 0; it < 64; it++)
        atomicAdd(&hist[w][srow[w][lane + 32 * it] >> 24], 1u);
    __syncwarp();

    unsigned prefix, prefmask, kk = TOPK;
    unsigned b1;
    {
        unsigned p = 0;
#pragma unroll
        for (int b = 0; b < 8; b++) p += hist[w][lane * 8 + b];
        unsigned S = p;
#pragma unroll
        for (int off = 1; off < 32; off <<= 1) {
            unsigned tv = __shfl_down_sync(0xffffffffu, S, off);
            if (lane + off < 32) S += tv;
        }
        unsigned sufExcl = S - p;
        bool mine = (S >= kk) && (sufExcl < kk);
        unsigned bal = __ballot_sync(0xffffffffu, mine);
        int src = __ffs(bal) - 1;
        unsigned chosen = 0, newk = 0;
        if (mine) {
            unsigned cum = sufExcl;
#pragma unroll
            for (int b = 7; b >= 0; b--) {
                unsigned h = hist[w][lane * 8 + b];
                if (cum + h >= kk) { chosen = lane * 8 + b; newk = kk - cum; break; }
                cum += h;
            }
        }
        b1 = __shfl_sync(0xffffffffu, chosen, src);
        kk = __shfl_sync(0xffffffffu, newk, src);
        prefix = b1 << 24;
        prefmask = 0xFF000000u;
    }
    __syncwarp();

    int cbase = 0;
    for (int it = 0; it < 64; it++) {
        int j = lane + 32 * it;
        bool isc = (srow[w][j] >> 24) == b1;
        unsigned bal = __ballot_sync(0xffffffffu, isc);
        if (isc) {
            int pos = cbase + __popc(bal & ((1u << lane) - 1u));
            if (pos < CAND_CAP) cand[w][pos] = (unsigned short)j;
        }
        cbase += __popc(bal);
    }
    __syncwarp();
    const bool useCand = (cbase <= CAND_CAP);
    const int c = cbase < CAND_CAP ? cbase : CAND_CAP;

#pragma unroll
    for (int shift = 16; shift >= 0; shift -= 8) {
#pragma unroll
        for (int e = 0; e < 8; e++) hist[w][lane + 32 * e] = 0;
        __syncwarp();
        if (useCand) {
            for (int e = lane; e < c; e += 32) {
                unsigned u = srow[w][cand[w][e]];
                if ((u & prefmask) == prefix)
                    atomicAdd(&hist[w][(u >> shift) & 255u], 1u);
            }
        } else {
            for (int it = 0; it < 64; it++) {
                unsigned u = srow[w][lane + 32 * it];
                if ((u & prefmask) == prefix)
                    atomicAdd(&hist[w][(u >> shift) & 255u], 1u);
            }
        }
        __syncwarp();
        unsigned p = 0;
#pragma unroll
        for (int b = 0; b < 8; b++) p += hist[w][lane * 8 + b];
        unsigned S = p;
#pragma unroll
        for (int off = 1; off < 32; off <<= 1) {
            unsigned tv = __shfl_down_sync(0xffffffffu, S, off);
            if (lane + off < 32) S += tv;
        }
        unsigned sufExcl = S - p;
        bool mine = (S >= kk) && (sufExcl < kk);
        unsigned bal = __ballot_sync(0xffffffffu, mine);
        int src = __ffs(bal) - 1;
        unsigned chosen = 0, newk = 0;
        if (mine) {
            unsigned cum = sufExcl;
#pragma unroll
            for (int b = 7; b >= 0; b--) {
                unsigned h = hist[w][lane * 8 + b];
                if (cum + h >= kk) { chosen = lane * 8 + b; newk = kk - cum; break; }
                cum += h;
            }
        }
        chosen = __shfl_sync(0xffffffffu, chosen, src);
        kk = __shfl_sync(0xffffffffu, newk, src);
        prefix |= chosen << shift;
        prefmask |= 0xFFu << shift;
        __syncwarp();
    }
    const unsigned tkey = prefix;

    float4* a4 = (float4*)(attn + R * SEQ);
    const float4 zero4 = make_float4(0.f, 0.f, 0.f, 0.f);
#pragma unroll
    for (int it = 0; it < 16; it++) a4[lane + 32 * it] = zero4;

    int base = 0;
    for (int it = 0; it < 64; it++) {
        int j = lane + 32 * it;
        bool keep = srow[w][j] >= tkey;
        unsigned bal = __ballot_sync(0xffffffffu, keep);
        if (keep) {
            int pos = base + __popc(bal & ((1u << lane) - 1u));
            if (pos < LCAP) list[w][pos] = j;
        }
        base += __popc(bal);
    }
    __syncwarp();
    const int n = base < LCAP ? base : LCAP;

    float lsum = 0.f;
    for (int e = lane; e < n; e += 32) {
        float s = unfkey(srow[w][list[w][e]]);
        float p = __expf(s - m);
        plist[w][e] = p;
        lsum += p;
    }
#pragma unroll
    for (int off = 16; off >= 1; off >>= 1)
        lsum += __shfl_xor_sync(0xffffffffu, lsum, off);
    const float inv = 1.0f / lsum;
    __syncwarp();

    const float* vb = v + (size_t)bh * SEQ * HD;
    float acc0 = 0.f, acc1 = 0.f;
    float* arow = attn + R * SEQ;
    float* mrow = maskp ? maskp + R * SEQ : (float*)0;
    for (int e = 0; e < n; e++) {
        int j = list[w][e];
        float wgt = plist[w][e] * inv;
        if (lane == 0) {
            arow[j] = wgt;
            if (mrow) mrow[j] = 0.f;
        }
        acc0 += wgt * vb[j * HD + lane];
        acc1 += wgt * vb[j * HD + lane + 32];
    }
    if (ctx) {
        ctx[R * HD + lane] = acc0;
        ctx[R * HD + lane + 32] = acc1;
    }
}

// ---------------------------------------------------------------------------
extern "C" void kernel_launch(void* const* d_in, const int* in_sizes, int n_in,
                              void* d_out, int out_size)
{
    if (n_in < 3 || !d_out) return;
    const float* q = (const float*)d_in[0];
    const float* k = (const float*)d_in[1];
    const float* v = (const float*)d_in[2];
    float* out = (float*)d_out;

    const size_t nctx = (size_t)NBH * SEQ * HD;        //   4,194,304
    const size_t nattn = (size_t)NBH * SEQ * SEQ;      // 134,217,728
    float* ctx = 0; float* attn = 0; float* maskp = 0;
    const size_t osz = (size_t)out_size;
    if (osz >= nctx + 2 * nattn) {
        ctx = out; attn = out + nctx; maskp = out + nctx + nattn;
    } else if (osz >= nctx + nattn) {
        ctx = out; attn = out + nctx;
    } else {
        attn = out;
    }

    static bool attr_done = false;
    if (!attr_done) {
        cudaFuncSetAttribute(score_kernel,
                             cudaFuncAttributeMaxDynamicSharedMemorySize, SCORE_SMEM);
        attr_done = true;
    }

    // Kernel 1 stages raw scores in the attn segment and prefills mask = 1.
    score_kernel<<<dim3(SEQ / 128, SEQ / 128, NBH), 256, SCORE_SMEM>>>(q, k, attn, maskp);
    finalize_kernel<<<(NBH * SEQ) / WPB, WPB * 32>>>(v, attn, ctx, attn, maskp);
}